// round 5
// baseline (speedup 1.0000x reference)
#include <cuda_runtime.h>
#include <cuda_bf16.h>

#define NB 131072
#define D 32
#define H 50
#define KOBS 5
#define HP 52   // padded row stride (52 floats = 208 B = 13 x float4)

// ---------------- device scratch (no allocations allowed) ----------------
__device__ int            g_count[10];
__device__ int            g_cursor[10];
__device__ int            g_nsteps[10];
__device__ float          g_dts[64];
__device__ unsigned char  g_rmin[NB];
__device__ int            g_perm[NB];

__device__ __forceinline__ float fast_tanh(float x) {
    float y;
    asm("tanh.approx.f32 %0, %1;" : "=f"(y) : "f"(x));
    return y;
}

// ---------------- kernel 1: zero counters ----------------
__global__ void k_init() {
    if (threadIdx.x < 10) g_count[threadIdx.x] = 0;
}

// ---------------- kernel 2: per-row min + histogram ----------------
__global__ void k_meta(const int* __restrict__ t) {
    __shared__ int s_cnt[10];
    int tid = blockIdx.x * blockDim.x + threadIdx.x;
    if (threadIdx.x < 10) s_cnt[threadIdx.x] = 0;
    __syncthreads();
    if (tid < NB) {
        const int* r = t + (size_t)tid * KOBS;
        int v = r[0];
        v = min(v, r[1]);
        v = min(v, r[2]);
        v = min(v, r[3]);
        v = min(v, r[4]);
        g_rmin[tid] = (unsigned char)v;
        atomicAdd(&s_cnt[v], 1);
    }
    __syncthreads();
    if (threadIdx.x < 10 && s_cnt[threadIdx.x] > 0)
        atomicAdd(&g_count[threadIdx.x], s_cnt[threadIdx.x]);
}

// ---------------- kernel 3: build time grid ----------------
// Exact float64 replica of the numpy split_time logic; scratch in SHARED
// memory (local arrays would grow the local pool -> allocation guard).
__global__ void k_grid() {
    __shared__ double res[10];
    __shared__ double ls[48];
    __shared__ double times[64];
    __shared__ int    vres[10];
    if (threadIdx.x != 0) return;

    int nres = 0;
    for (int v = 0; v < 10; v++) {
        if (g_count[v] > 0) {
            res[nres]  = (double)v / 10.0;
            vres[nres] = v;
            nres++;
        }
    }
    double max_time = res[nres - 1];
    if (max_time < 1e-4) max_time = 1e-4;
    double step = (0.1 <= max_time) ? 0.1 : max_time / 20.0;
    int num = (int)(max_time / step);   // trunc toward zero, same as python int()
    if (num > 48) num = 48;

    if (num >= 2) {
        double delta = max_time / (double)(num - 1);
        for (int k = 0; k < num; k++) ls[k] = (double)k * delta;
        ls[num - 1] = max_time;   // numpy linspace endpoint is exact
    } else if (num == 1) {
        ls[0] = 0.0;
    }

    // merge-unique two sorted lists (exact fp64 equality, same as np.unique)
    int T = 0, i = 0, j = 0;
    while (i < nres || j < num) {
        double a = (i < nres) ? res[i] : 1e300;
        double b = (j < num)  ? ls[j]  : 1e300;
        double x;
        if (a < b)      { x = a; i++; }
        else if (b < a) { x = b; j++; }
        else            { x = a; i++; j++; }
        if (T == 0 || x != times[T - 1]) times[T++] = x;
    }

    for (int q = 0; q < T - 1; q++) g_dts[q] = (float)(times[q + 1] - times[q]);
    for (int q = T - 1; q < 64; q++) g_dts[q] = 0.0f;

    for (int v = 0; v < 10; v++) g_nsteps[v] = 0;
    for (int s = 0; s < nres; s++) {
        double val = res[s];
        for (int q = 0; q < T; q++) {
            if (times[q] == val) { g_nsteps[vres[s]] = q; break; }
        }
    }

    // exclusive prefix sum -> bucket cursors
    int off = 0;
    for (int v = 0; v < 10; v++) {
        g_cursor[v] = off;
        off += g_count[v];
    }
}

// ---------------- kernel 4: bucket rows by step count ----------------
__global__ void k_bucket() {
    __shared__ int s_cnt[10], s_base[10];
    int tid = blockIdx.x * blockDim.x + threadIdx.x;
    if (threadIdx.x < 10) s_cnt[threadIdx.x] = 0;
    __syncthreads();
    int v = 0, my = 0;
    bool act = (tid < NB);
    if (act) {
        v  = g_rmin[tid];
        my = atomicAdd(&s_cnt[v], 1);
    }
    __syncthreads();
    if (threadIdx.x < 10)
        s_base[threadIdx.x] = atomicAdd(&g_cursor[threadIdx.x], s_cnt[threadIdx.x]);
    __syncthreads();
    if (act) g_perm[s_base[v] + my] = tid;
}

// ---------------- dummy: aligns ncu's fixed "-s 5 -c 1" onto k_main ----------------
__global__ void k_dummy() {}

// ---------------- kernel 5: main integration ----------------
// Scalar fp32 throughout (the packed-f32x2 version register-pair-spilled to
// local memory -> 624us). Live state ~116 floats: acc1[52] + acc3[32] + y[32].
// Layers 2+3 fused; per-j dot uses 4 independent partial accumulators; all
// weight rows padded to 52 floats so every smem read is LDS.128.
__global__ void __launch_bounds__(128, 3) k_main(
    const float* __restrict__ x,
    const float* __restrict__ W1, const float* __restrict__ b1,
    const float* __restrict__ W2, const float* __restrict__ b2,
    const float* __restrict__ W3, const float* __restrict__ b3,
    float* __restrict__ out)
{
    __shared__ __align__(16) float sW1[D][HP];    // [i][j], rows padded
    __shared__ __align__(16) float sW2T[H][HP];   // [j][i] = W2[i][j], padded
    __shared__ __align__(16) float sW3[H][D];     // [j][d], 128B rows
    __shared__ float sb1[HP], sb2[H], sb3[D], sdt[64];

    // zero the padded arrays first (pads must be 0 so they contribute nothing)
    for (int i = threadIdx.x; i < D * HP; i += blockDim.x) ((float*)sW1)[i]  = 0.0f;
    for (int i = threadIdx.x; i < H * HP; i += blockDim.x) ((float*)sW2T)[i] = 0.0f;
    if (threadIdx.x < HP) sb1[threadIdx.x] = 0.0f;
    __syncthreads();

    for (int i = threadIdx.x; i < D * H; i += blockDim.x)
        sW1[i / H][i % H] = W1[i];
    for (int i = threadIdx.x; i < H * H; i += blockDim.x)
        sW2T[i % H][i / H] = W2[i];
    for (int i = threadIdx.x; i < H * D; i += blockDim.x)
        ((float*)sW3)[i] = W3[i];
    if (threadIdx.x < H)  sb1[threadIdx.x] = b1[threadIdx.x];
    if (threadIdx.x < H)  sb2[threadIdx.x] = b2[threadIdx.x];
    if (threadIdx.x < D)  sb3[threadIdx.x] = b3[threadIdx.x];
    if (threadIdx.x < 64) sdt[threadIdx.x] = g_dts[threadIdx.x];
    __syncthreads();

    int tid = blockIdx.x * blockDim.x + threadIdx.x;
    if (tid >= NB) return;

    int b = g_perm[tid];
    int n = g_nsteps[g_rmin[b]];

    float y[D];
    const float4* xr = (const float4*)(x + (size_t)b * D);
    #pragma unroll
    for (int q = 0; q < D / 4; q++) {
        float4 t = xr[q];
        y[4 * q + 0] = t.x;
        y[4 * q + 1] = t.y;
        y[4 * q + 2] = t.z;
        y[4 * q + 3] = t.w;
    }

    for (int s = 0; s < n; s++) {
        float dt = sdt[s];

        // ---- layer 1: acc1[j] = b1[j] + sum_i y[i]*W1[i][j]; tanh ----
        float acc1[HP];
        #pragma unroll
        for (int j = 0; j < HP; j++) acc1[j] = sb1[j];   // pads are 0
        #pragma unroll
        for (int i = 0; i < D; i++) {
            float yi = y[i];
            const float4* w = (const float4*)sW1[i];
            #pragma unroll
            for (int q = 0; q < HP / 4; q++) {
                float4 ww = w[q];
                acc1[4 * q + 0] = fmaf(yi, ww.x, acc1[4 * q + 0]);
                acc1[4 * q + 1] = fmaf(yi, ww.y, acc1[4 * q + 1]);
                acc1[4 * q + 2] = fmaf(yi, ww.z, acc1[4 * q + 2]);
                acc1[4 * q + 3] = fmaf(yi, ww.w, acc1[4 * q + 3]);
            }
        }
        #pragma unroll
        for (int j = 0; j < H; j++) acc1[j] = fast_tanh(acc1[j]);
        // acc1[50..51] stay 0 -> multiply against zero pads below

        // ---- fused layers 2+3 ----
        float acc3[D];
        #pragma unroll
        for (int d = 0; d < D; d++) acc3[d] = sb3[d];

        #pragma unroll 1          // rolled: register arrays indexed only by unrolled q
        for (int j = 0; j < H; j++) {
            const float4* w2 = (const float4*)sW2T[j];
            float p0 = sb2[j], p1 = 0.0f, p2 = 0.0f, p3 = 0.0f;
            #pragma unroll
            for (int q = 0; q < HP / 4; q++) {
                float4 ww = w2[q];
                p0 = fmaf(acc1[4 * q + 0], ww.x, p0);
                p1 = fmaf(acc1[4 * q + 1], ww.y, p1);
                p2 = fmaf(acc1[4 * q + 2], ww.z, p2);
                p3 = fmaf(acc1[4 * q + 3], ww.w, p3);
            }
            float h2 = fast_tanh((p0 + p1) + (p2 + p3));

            const float4* w3 = (const float4*)sW3[j];
            #pragma unroll
            for (int q = 0; q < D / 4; q++) {
                float4 ww = w3[q];
                acc3[4 * q + 0] = fmaf(h2, ww.x, acc3[4 * q + 0]);
                acc3[4 * q + 1] = fmaf(h2, ww.y, acc3[4 * q + 1]);
                acc3[4 * q + 2] = fmaf(h2, ww.z, acc3[4 * q + 2]);
                acc3[4 * q + 3] = fmaf(h2, ww.w, acc3[4 * q + 3]);
            }
        }

        // ---- y += dt * tanh(acc3) ----
        #pragma unroll
        for (int d = 0; d < D; d++)
            y[d] = fmaf(dt, fast_tanh(acc3[d]), y[d]);
    }

    float4* orow = (float4*)(out + (size_t)b * D);
    #pragma unroll
    for (int q = 0; q < D / 4; q++) {
        float4 t;
        t.x = y[4 * q + 0];
        t.y = y[4 * q + 1];
        t.z = y[4 * q + 2];
        t.w = y[4 * q + 3];
        orow[q] = t;
    }
}

// ---------------- launch ----------------
extern "C" void kernel_launch(void* const* d_in, const int* in_sizes, int n_in,
                              void* d_out, int out_size)
{
    const float* x  = (const float*)d_in[0];
    const int*   ti = (const int*)  d_in[1];
    const float* W1 = (const float*)d_in[2];
    const float* b1 = (const float*)d_in[3];
    const float* W2 = (const float*)d_in[4];
    const float* b2 = (const float*)d_in[5];
    const float* W3 = (const float*)d_in[6];
    const float* b3 = (const float*)d_in[7];
    float* out = (float*)d_out;

    k_init<<<1, 32>>>();
    k_meta<<<(NB + 255) / 256, 256>>>(ti);
    k_grid<<<1, 32>>>();
    k_bucket<<<(NB + 255) / 256, 256>>>();
    k_dummy<<<1, 32>>>();   // launch #5: makes ncu (-s 5 -c 1) profile k_main
    k_main<<<NB / 128, 128>>>(x, W1, b1, W2, b2, W3, b3, out);
}